// round 16
// baseline (speedup 1.0000x reference)
#include <cuda_runtime.h>
#include <cuda_bf16.h>

#define NTOK 4096
#define HEADS 8
#define DH 128
#define NKEY 256
#define TOPK 32

static __device__ __forceinline__ float neg_inf() { return __int_as_float(0xff800000); }

// order-preserving float<->uint (total order, no NaNs here)
static __device__ __forceinline__ unsigned ford(float f) {
    unsigned b = __float_as_uint(f);
    return (b & 0x80000000u) ? ~b : (b | 0x80000000u);
}
static __device__ __forceinline__ float forddec(unsigned u) {
    unsigned b = (u & 0x80000000u) ? (u & 0x7fffffffu) : ~u;
    return __uint_as_float(b);
}

// ---------------- scratch (no allocations allowed) ----------------
__device__ float g_q [(size_t)NTOK * 2048];
__device__ float g_s1[(size_t)NTOK * HEADS * 2 * TOPK];
__device__ int   g_i1[(size_t)NTOK * HEADS * 2 * TOPK];
__device__ float g_oh[(size_t)NTOK * 1024];

// ---------------- tf32 helpers ----------------
static __device__ __forceinline__ void mma1688(float* d, const unsigned* a, const unsigned* b) {
    asm volatile(
        "mma.sync.aligned.m16n8k8.row.col.f32.tf32.tf32.f32 "
        "{%0,%1,%2,%3}, {%4,%5,%6,%7}, {%8,%9}, {%0,%1,%2,%3};"
        : "+f"(d[0]), "+f"(d[1]), "+f"(d[2]), "+f"(d[3])
        : "r"(a[0]), "r"(a[1]), "r"(a[2]), "r"(a[3]), "r"(b[0]), "r"(b[1]));
}
static __device__ __forceinline__ unsigned f2tf32(float f) {
    unsigned r; asm("cvt.rna.tf32.f32 %0, %1;" : "=r"(r) : "f"(f)); return r;
}
static __device__ __forceinline__ void split_tf32(float f, unsigned& hi, unsigned& lo) {
    hi = f2tf32(f);
    lo = f2tf32(f - __uint_as_float(hi));
}

// =================================================================
// Split-tf32 GEMM (selection-safe ~fp32): C = A[M,K] * B[N,K]^T.
// A and B are split hi/lo ONCE at smem-store; inner loop is pure
// LDS + HMMA. Single-buffered (40KB smem), 128x128x16, 8 warps.
// =================================================================
__global__ __launch_bounds__(256, 1)
void mma_split_tn(const float* __restrict__ A, const float* __restrict__ B,
                  float* __restrict__ C,
                  int M, int N, int K, int lda, int ldb, int ldc)
{
    __shared__ unsigned Ahi[128][20], Alo[128][20];
    __shared__ unsigned Bhi[128][20], Blo[128][20];

    const int tid  = threadIdx.x;
    const int lane = tid & 31;
    const int wid  = tid >> 5;
    const int wm   = wid & 3;
    const int wn   = wid >> 2;
    const int m0   = blockIdx.y * 128;
    const int n0   = blockIdx.x * 128;

    const int r0 = tid >> 2;
    const int r1 = r0 + 64;
    const int kc = (tid & 3) << 2;

    const float* Ap0 = A + (size_t)(m0 + r0) * lda + kc;
    const float* Ap1 = A + (size_t)(m0 + r1) * lda + kc;
    const float* Bp0 = B + (size_t)(n0 + r0) * ldb + kc;
    const float* Bp1 = B + (size_t)(n0 + r1) * ldb + kc;

    float4 ra0 = *(const float4*)Ap0;
    float4 ra1 = *(const float4*)Ap1;
    float4 rb0 = *(const float4*)Bp0;
    float4 rb1 = *(const float4*)Bp1;

    float d[2][8][4];
    #pragma unroll
    for (int mt = 0; mt < 2; mt++)
        #pragma unroll
        for (int nt = 0; nt < 8; nt++)
            #pragma unroll
            for (int i = 0; i < 4; i++) d[mt][nt][i] = 0.f;

    const int frow = lane >> 2;
    const int fcol = lane & 3;
    const int nsteps = K >> 4;

    auto store_tile = [&](const float4& a0, const float4& a1,
                          const float4& b0, const float4& b1) {
        unsigned h0,l0,h1,l1,h2,l2,h3,l3;
        split_tf32(a0.x,h0,l0); split_tf32(a0.y,h1,l1);
        split_tf32(a0.z,h2,l2); split_tf32(a0.w,h3,l3);
        *(uint4*)&Ahi[r0][kc] = make_uint4(h0,h1,h2,h3);
        *(uint4*)&Alo[r0][kc] = make_uint4(l0,l1,l2,l3);
        split_tf32(a1.x,h0,l0); split_tf32(a1.y,h1,l1);
        split_tf32(a1.z,h2,l2); split_tf32(a1.w,h3,l3);
        *(uint4*)&Ahi[r1][kc] = make_uint4(h0,h1,h2,h3);
        *(uint4*)&Alo[r1][kc] = make_uint4(l0,l1,l2,l3);
        split_tf32(b0.x,h0,l0); split_tf32(b0.y,h1,l1);
        split_tf32(b0.z,h2,l2); split_tf32(b0.w,h3,l3);
        *(uint4*)&Bhi[r0][kc] = make_uint4(h0,h1,h2,h3);
        *(uint4*)&Blo[r0][kc] = make_uint4(l0,l1,l2,l3);
        split_tf32(b1.x,h0,l0); split_tf32(b1.y,h1,l1);
        split_tf32(b1.z,h2,l2); split_tf32(b1.w,h3,l3);
        *(uint4*)&Bhi[r1][kc] = make_uint4(h0,h1,h2,h3);
        *(uint4*)&Blo[r1][kc] = make_uint4(l0,l1,l2,l3);
    };

    store_tile(ra0, ra1, rb0, rb1);

    for (int s = 0; s < nsteps; s++) {
        __syncthreads();                   // stores visible
        if (s + 1 < nsteps) {              // prefetch next tile (hidden by compute)
            ra0 = *(const float4*)(Ap0 + (s+1)*16);
            ra1 = *(const float4*)(Ap1 + (s+1)*16);
            rb0 = *(const float4*)(Bp0 + (s+1)*16);
            rb1 = *(const float4*)(Bp1 + (s+1)*16);
        }
        #pragma unroll
        for (int k0 = 0; k0 < 16; k0 += 8) {
            unsigned ah[2][4], al[2][4];
            #pragma unroll
            for (int mt = 0; mt < 2; mt++) {
                const int mb = wm*32 + mt*16;
                ah[mt][0] = Ahi[mb + frow    ][k0 + fcol    ];
                ah[mt][1] = Ahi[mb + frow + 8][k0 + fcol    ];
                ah[mt][2] = Ahi[mb + frow    ][k0 + fcol + 4];
                ah[mt][3] = Ahi[mb + frow + 8][k0 + fcol + 4];
                al[mt][0] = Alo[mb + frow    ][k0 + fcol    ];
                al[mt][1] = Alo[mb + frow + 8][k0 + fcol    ];
                al[mt][2] = Alo[mb + frow    ][k0 + fcol + 4];
                al[mt][3] = Alo[mb + frow + 8][k0 + fcol + 4];
            }
            #pragma unroll
            for (int nt = 0; nt < 8; nt++) {
                const int n = wn*64 + nt*8 + frow;
                unsigned bh[2], bl[2];
                bh[0] = Bhi[n][k0 + fcol    ];
                bh[1] = Bhi[n][k0 + fcol + 4];
                bl[0] = Blo[n][k0 + fcol    ];
                bl[1] = Blo[n][k0 + fcol + 4];
                mma1688(d[0][nt], ah[0], bh);
                mma1688(d[0][nt], ah[0], bl);
                mma1688(d[0][nt], al[0], bh);
                mma1688(d[1][nt], ah[1], bh);
                mma1688(d[1][nt], ah[1], bl);
                mma1688(d[1][nt], al[1], bh);
            }
        }
        __syncthreads();                   // everyone done reading
        if (s + 1 < nsteps) store_tile(ra0, ra1, rb0, rb1);
    }

    #pragma unroll
    for (int mt = 0; mt < 2; mt++) {
        const int row = m0 + wm*32 + mt*16 + frow;
        #pragma unroll
        for (int nt = 0; nt < 8; nt++) {
            const int col = n0 + wn*64 + nt*8 + fcol*2;
            *(float2*)&C[(size_t)row * ldc + col] =
                make_float2(d[mt][nt][0], d[mt][nt][1]);
            *(float2*)&C[(size_t)(row + 8) * ldc + col] =
                make_float2(d[mt][nt][2], d[mt][nt][3]);
        }
    }
}

// =================================================================
// Single-pass tf32 GEMM (~1e-4, for the tolerance-checked output):
// both operands cvt'd to tf32 at smem-store; pure LDS+HMMA inner
// loop; double-buffered (40KB), 2 CTA/SM.
// =================================================================
__global__ __launch_bounds__(256, 2)
void mma_tf32_tn(const float* __restrict__ A, const float* __restrict__ B,
                 float* __restrict__ C, const float* __restrict__ bias,
                 int M, int N, int K, int lda, int ldb, int ldc)
{
    __shared__ unsigned Ah[2][128][20];
    __shared__ unsigned Bh[2][128][20];

    const int tid  = threadIdx.x;
    const int lane = tid & 31;
    const int wid  = tid >> 5;
    const int wm   = wid & 3;
    const int wn   = wid >> 2;
    const int m0   = blockIdx.y * 128;
    const int n0   = blockIdx.x * 128;

    const int r0 = tid >> 2;
    const int r1 = r0 + 64;
    const int kc = (tid & 3) << 2;

    const float* Ap0 = A + (size_t)(m0 + r0) * lda + kc;
    const float* Ap1 = A + (size_t)(m0 + r1) * lda + kc;
    const float* Bp0 = B + (size_t)(n0 + r0) * ldb + kc;
    const float* Bp1 = B + (size_t)(n0 + r1) * ldb + kc;

    float4 ra0 = *(const float4*)Ap0;
    float4 ra1 = *(const float4*)Ap1;
    float4 rb0 = *(const float4*)Bp0;
    float4 rb1 = *(const float4*)Bp1;

    float d[2][8][4];
    #pragma unroll
    for (int mt = 0; mt < 2; mt++)
        #pragma unroll
        for (int nt = 0; nt < 8; nt++)
            #pragma unroll
            for (int i = 0; i < 4; i++) d[mt][nt][i] = 0.f;

    const int frow = lane >> 2;
    const int fcol = lane & 3;
    const int nsteps = K >> 4;

    auto store_tile = [&](int buf, const float4& a0, const float4& a1,
                          const float4& b0, const float4& b1) {
        *(uint4*)&Ah[buf][r0][kc] = make_uint4(f2tf32(a0.x), f2tf32(a0.y),
                                               f2tf32(a0.z), f2tf32(a0.w));
        *(uint4*)&Ah[buf][r1][kc] = make_uint4(f2tf32(a1.x), f2tf32(a1.y),
                                               f2tf32(a1.z), f2tf32(a1.w));
        *(uint4*)&Bh[buf][r0][kc] = make_uint4(f2tf32(b0.x), f2tf32(b0.y),
                                               f2tf32(b0.z), f2tf32(b0.w));
        *(uint4*)&Bh[buf][r1][kc] = make_uint4(f2tf32(b1.x), f2tf32(b1.y),
                                               f2tf32(b1.z), f2tf32(b1.w));
    };

    store_tile(0, ra0, ra1, rb0, rb1);
    __syncthreads();

    for (int s = 0; s < nsteps; s++) {
        const int cur = s & 1;
        const int nxt = cur ^ 1;
        if (s + 1 < nsteps) {
            ra0 = *(const float4*)(Ap0 + (s+1)*16);
            ra1 = *(const float4*)(Ap1 + (s+1)*16);
            rb0 = *(const float4*)(Bp0 + (s+1)*16);
            rb1 = *(const float4*)(Bp1 + (s+1)*16);
        }
        #pragma unroll
        for (int k0 = 0; k0 < 16; k0 += 8) {
            unsigned ah[2][4];
            #pragma unroll
            for (int mt = 0; mt < 2; mt++) {
                const int mb = wm*32 + mt*16;
                ah[mt][0] = Ah[cur][mb + frow    ][k0 + fcol    ];
                ah[mt][1] = Ah[cur][mb + frow + 8][k0 + fcol    ];
                ah[mt][2] = Ah[cur][mb + frow    ][k0 + fcol + 4];
                ah[mt][3] = Ah[cur][mb + frow + 8][k0 + fcol + 4];
            }
            #pragma unroll
            for (int nt = 0; nt < 8; nt++) {
                const int n = wn*64 + nt*8 + frow;
                unsigned bh[2];
                bh[0] = Bh[cur][n][k0 + fcol    ];
                bh[1] = Bh[cur][n][k0 + fcol + 4];
                mma1688(d[0][nt], ah[0], bh);
                mma1688(d[1][nt], ah[1], bh);
            }
        }
        if (s + 1 < nsteps) store_tile(nxt, ra0, ra1, rb0, rb1);
        __syncthreads();
    }

    #pragma unroll
    for (int mt = 0; mt < 2; mt++) {
        const int row = m0 + wm*32 + mt*16 + frow;
        #pragma unroll
        for (int nt = 0; nt < 8; nt++) {
            const int col = n0 + wn*64 + nt*8 + fcol*2;
            float2 bv = make_float2(0.f, 0.f);
            if (bias) bv = *(const float2*)(bias + col);
            *(float2*)&C[(size_t)row * ldc + col] =
                make_float2(d[mt][nt][0] + bv.x, d[mt][nt][1] + bv.y);
            *(float2*)&C[(size_t)(row + 8) * ldc + col] =
                make_float2(d[mt][nt][2] + bv.x, d[mt][nt][3] + bv.y);
        }
    }
}

// =================================================================
// Kernel 2: dots (one (h,p), 32-token tile vs 256 keys) + top-32.
// Extraction: 4 interleaved chains/warp, REDUX + ballot per round.
// =================================================================
__global__ __launch_bounds__(256)
void dots_topk_kernel(const float* __restrict__ qm, const float* __restrict__ keys)
{
    __shared__ float As[8][36];
    __shared__ float Bs[8][264];
    __shared__ float dsm[32*256];

    const int tid  = threadIdx.x;
    const int hp   = blockIdx.y;
    const int h    = hp >> 1;
    const int p    = hp & 1;
    const int t0g  = blockIdx.x * 32;

    const int ty   = tid >> 5;
    const int lane = tid & 31;

    const int at = tid >> 1;
    const int ak = (tid & 1) << 2;
    const float* Ap = qm + (size_t)(t0g + at) * 2048 + p*1024 + h*DH + ak;

    const int bn0 = tid >> 1;
    const int bn1 = bn0 + 128;
    const int bk  = (tid & 1) << 2;
    const float* Kb  = keys + (size_t)h * (NKEY*2*DH) + (size_t)p * DH;
    const float* Bp0 = Kb + (size_t)bn0 * (2*DH) + bk;
    const float* Bp1 = Kb + (size_t)bn1 * (2*DH) + bk;

    float4 ra = make_float4(0.f,0.f,0.f,0.f);
    if (tid < 64) ra = *(const float4*)Ap;
    float4 rb0 = *(const float4*)Bp0;
    float4 rb1 = *(const float4*)Bp1;

    float acc[4][8];
    #pragma unroll
    for (int r = 0; r < 4; r++)
        #pragma unroll
        for (int c = 0; c < 8; c++) acc[r][c] = 0.f;

    for (int s = 0; s < 16; s++) {
        __syncthreads();
        if (tid < 64) {
            As[ak+0][at] = ra.x; As[ak+1][at] = ra.y;
            As[ak+2][at] = ra.z; As[ak+3][at] = ra.w;
        }
        Bs[bk+0][bn0] = rb0.x; Bs[bk+1][bn0] = rb0.y;
        Bs[bk+2][bn0] = rb0.z; Bs[bk+3][bn0] = rb0.w;
        Bs[bk+0][bn1] = rb1.x; Bs[bk+1][bn1] = rb1.y;
        Bs[bk+2][bn1] = rb1.z; Bs[bk+3][bn1] = rb1.w;
        __syncthreads();
        if (s + 1 < 16) {
            if (tid < 64) ra = *(const float4*)(Ap + (s+1)*8);
            rb0 = *(const float4*)(Bp0 + (s+1)*8);
            rb1 = *(const float4*)(Bp1 + (s+1)*8);
        }
        #pragma unroll
        for (int kk = 0; kk < 8; kk++) {
            float4 a4 = *(const float4*)&As[kk][ty*4];
            float4 b0 = *(const float4*)&Bs[kk][lane*4];
            float4 b1 = *(const float4*)&Bs[kk][128 + lane*4];
            float ar[4] = {a4.x,a4.y,a4.z,a4.w};
            float bc[8] = {b0.x,b0.y,b0.z,b0.w,b1.x,b1.y,b1.z,b1.w};
            #pragma unroll
            for (int r = 0; r < 4; r++)
                #pragma unroll
                for (int c = 0; c < 8; c++)
                    acc[r][c] = fmaf(ar[r], bc[c], acc[r][c]);
        }
    }

    #pragma unroll
    for (int r = 0; r < 4; r++) {
        *(float4*)&dsm[(ty*4+r)*256 + lane*4]       = make_float4(acc[r][0],acc[r][1],acc[r][2],acc[r][3]);
        *(float4*)&dsm[(ty*4+r)*256 + 128 + lane*4] = make_float4(acc[r][4],acc[r][5],acc[r][6],acc[r][7]);
    }
    __syncthreads();

    float v[4][8];
    #pragma unroll
    for (int c = 0; c < 4; c++)
        #pragma unroll
        for (int j = 0; j < 8; j++)
            v[c][j] = dsm[(ty*4+c)*256 + j*32 + lane];

    unsigned taken[4] = {0u,0u,0u,0u};
    float outv[4] = {0.f,0.f,0.f,0.f};
    int   outn[4] = {0,0,0,0};

    #pragma unroll 1
    for (int kk = 0; kk < 32; kk++) {
        unsigned u[4]; int ln[4];
        #pragma unroll
        for (int c = 0; c < 4; c++) {
            float lv = neg_inf(); int l = 0x7fffffff;
            #pragma unroll
            for (int j = 0; j < 8; j++) {
                float cand = ((taken[c] >> j) & 1u) ? neg_inf() : v[c][j];
                if (cand > lv) { lv = cand; l = j*32 + lane; }
            }
            u[c] = ford(lv); ln[c] = l;
        }
        unsigned umax[4];
        #pragma unroll
        for (int c = 0; c < 4; c++) umax[c] = __reduce_max_sync(0xffffffffu, u[c]);
        unsigned ball[4];
        #pragma unroll
        for (int c = 0; c < 4; c++) ball[c] = __ballot_sync(0xffffffffu, u[c] == umax[c]);
        #pragma unroll
        for (int c = 0; c < 4; c++) {
            const int wl = __ffs(ball[c]) - 1;
            const int wn = __shfl_sync(0xffffffffu, ln[c], wl);
            if (kk == lane) { outv[c] = forddec(umax[c]); outn[c] = wn; }
            if (wl == lane) taken[c] |= 1u << (ln[c] >> 5);
        }
    }

    #pragma unroll
    for (int c = 0; c < 4; c++) {
        const size_t base = ((((size_t)(t0g + ty*4 + c)) * HEADS + h) * 2 + p) * TOPK;
        g_s1[base + lane] = outv[c];
        g_i1[base + lane] = outn[c];
    }
}

// =================================================================
// Kernel 3: combine, 2 slots/warp, software-pipelined gather.
// =================================================================
__global__ __launch_bounds__(256)
void combine_kernel(const float* __restrict__ values)
{
    const int warp  = threadIdx.x >> 5;
    const int lane  = threadIdx.x & 31;
    const int slotA = blockIdx.x * 16 + warp * 2;
    const int t  = slotA & 2047;
    const int h  = (slotA >> 11) & 7;
    const int b  = slotA >> 14;
    const int u  = t >> 1;

    const size_t b0A = ((((size_t)(b*2048 + u))        * HEADS + h) * 2 + 0) * TOPK;
    const size_t b1A = ((((size_t)(b*2048 + u + 1024)) * HEADS + h) * 2 + 0) * TOPK;
    const size_t b0B = b0A + TOPK;
    const size_t b1B = b1A + TOPK;

    const float s0A = g_s1[b0A + lane]; const int i0A = g_i1[b0A + lane];
    const float s1A = g_s1[b1A + lane]; const int i1A = g_i1[b1A + lane];
    const float s0B = g_s1[b0B + lane]; const int i0B = g_i1[b0B + lane];
    const float s1B = g_s1[b1B + lane]; const int i1B = g_i1[b1B + lane];

    int ptrA = 0, ptrB = 0;
    float rvA = 0.f, rvB = 0.f; int rfA = 0, rfB = 0;
    #pragma unroll 1
    for (int it = 0; it < 32; it++) {
        const int ppA = ptrA < 32 ? ptrA : 31;
        const int ppB = ptrB < 32 ? ptrB : 31;
        float cvA = __shfl_sync(0xffffffffu, s0A, ppA) + s1A;
        float cvB = __shfl_sync(0xffffffffu, s0B, ppB) + s1B;
        int flA = ptrA * 32 + lane;
        int flB = ptrB * 32 + lane;
        if (ptrA >= 32) { cvA = neg_inf(); flA = 0x7fffffff; }
        if (ptrB >= 32) { cvB = neg_inf(); flB = 0x7fffffff; }
        const unsigned uA = ford(cvA), uB = ford(cvB);
        const unsigned umA = __reduce_max_sync(0xffffffffu, uA);
        const unsigned umB = __reduce_max_sync(0xffffffffu, uB);
        const unsigned baA = __ballot_sync(0xffffffffu, uA == umA);
        const unsigned baB = __ballot_sync(0xffffffffu, uB == umB);
        const int wlA = __ffs(baA) - 1;
        const int wlB = __ffs(baB) - 1;
        const int wfA = __shfl_sync(0xffffffffu, flA, wlA);
        const int wfB = __shfl_sync(0xffffffffu, flB, wlB);
        if (it == lane) { rvA = forddec(umA); rfA = wfA;
                          rvB = forddec(umB); rfB = wfB; }
        if (wlA == lane && flA != 0x7fffffff) ptrA++;
        if (wlB == lane && flB != 0x7fffffff) ptrB++;
    }

    const float mxA = __shfl_sync(0xffffffffu, rvA, 0);
    const float mxB = __shfl_sync(0xffffffffu, rvB, 0);
    float eA = __expf(rvA - mxA);
    float eB = __expf(rvB - mxB);
    float sA = eA, sB = eB;
    #pragma unroll
    for (int o = 16; o > 0; o >>= 1) {
        sA += __shfl_xor_sync(0xffffffffu, sA, o);
        sB += __shfl_xor_sync(0xffffffffu, sB, o);
    }
    const float wA = eA / sA;
    const float wB = eB / sB;

    const int viA = __shfl_sync(0xffffffffu, i0A, rfA >> 5) * NKEY
                  + __shfl_sync(0xffffffffu, i1A, rfA & 31);
    const int viB = __shfl_sync(0xffffffffu, i0B, rfB >> 5) * NKEY
                  + __shfl_sync(0xffffffffu, i1B, rfB & 31);

    const float* vb = values + (size_t)h * ((size_t)NKEY*NKEY) * DH;
    float4 accA = make_float4(0.f,0.f,0.f,0.f);
    float4 accB = make_float4(0.f,0.f,0.f,0.f);

    #pragma unroll 1
    for (int k0 = 0; k0 < 32; k0 += 8) {
        int   iA[8], iB[8];
        float fA[8], fB[8];
        #pragma unroll
        for (int j = 0; j < 8; j++) {
            iA[j] = __shfl_sync(0xffffffffu, viA, k0 + j);
            fA[j] = __shfl_sync(0xffffffffu, wA,  k0 + j);
            iB[j] = __shfl_sync(0xffffffffu, viB, k0 + j);
            fB[j] = __shfl_sync(0xffffffffu, wB,  k0 + j);
        }
        float4 rA[8], rB[8];
        #pragma unroll
        for (int j = 0; j < 8; j++) {
            rA[j] = *(const float4*)(vb + (size_t)iA[j] * DH + lane*4);
            rB[j] = *(const float4*)(vb + (size_t)iB[j] * DH + lane*4);
        }
        #pragma unroll
        for (int j = 0; j < 8; j++) {
            accA.x = fmaf(fA[j], rA[j].x, accA.x);
            accA.y = fmaf(fA[j], rA[j].y, accA.y);
            accA.z = fmaf(fA[j], rA[j].z, accA.z);
            accA.w = fmaf(fA[j], rA[j].w, accA.w);
            accB.x = fmaf(fB[j], rB[j].x, accB.x);
            accB.y = fmaf(fB[j], rB[j].y, accB.y);
            accB.z = fmaf(fB[j], rB[j].z, accB.z);
            accB.w = fmaf(fB[j], rB[j].w, accB.w);
        }
    }

    *(float4*)&g_oh[(size_t)(b*2048 + t)     * 1024 + h*DH + lane*4] = accA;
    *(float4*)&g_oh[(size_t)(b*2048 + t + 1) * 1024 + h*DH + lane*4] = accB;
}

// =================================================================
extern "C" void kernel_launch(void* const* d_in, const int* in_sizes, int n_in,
                              void* d_out, int out_size)
{
    const float* x      = (const float*)d_in[0];
    const float* Wq     = (const float*)d_in[1];
    const float* keys   = (const float*)d_in[2];
    const float* values = (const float*)d_in[3];
    const float* Wo     = (const float*)d_in[4];
    const float* bo     = (const float*)d_in[5];
    float* out = (float*)d_out;

    float* q;  cudaGetSymbolAddress((void**)&q,  g_q);
    float* oh; cudaGetSymbolAddress((void**)&oh, g_oh);

    // 1) q = x @ Wq^T (selection path -> split precision, zero in-loop ALU)
    mma_split_tn<<<dim3(2048/128, 4096/128), 256>>>(x, Wq, q,
                                                    4096, 2048, 1024, 1024, 1024, 2048);
    // 2) dots + stage-1 top-32
    dots_topk_kernel<<<dim3(4096/32, 16), 256>>>(q, keys);
    // 3) combine + softmax + gather
    combine_kernel<<<2048, 256>>>(values);
    // 4) out = oh @ Wo^T + bo (tolerance-checked -> single-pass tf32)
    mma_tf32_tn<<<dim3(1024/128, 4096/128), 256>>>(oh, Wo, out, bo,
                                                   4096, 1024, 1024, 1024, 1024, 1024);
}

// round 17
// speedup vs baseline: 1.5907x; 1.5907x over previous
#include <cuda_runtime.h>
#include <cuda_bf16.h>

#define NTOK 4096
#define HEADS 8
#define DH 128
#define NKEY 256
#define TOPK 32

static __device__ __forceinline__ float neg_inf() { return __int_as_float(0xff800000); }

// order-preserving float<->uint (total order, no NaNs here)
static __device__ __forceinline__ unsigned ford(float f) {
    unsigned b = __float_as_uint(f);
    return (b & 0x80000000u) ? ~b : (b | 0x80000000u);
}
static __device__ __forceinline__ float forddec(unsigned u) {
    unsigned b = (u & 0x80000000u) ? (u & 0x7fffffffu) : ~u;
    return __uint_as_float(b);
}

// ---------------- scratch (no allocations allowed) ----------------
__device__ float g_q [(size_t)NTOK * 2048];
__device__ float g_s1[(size_t)NTOK * HEADS * 2 * TOPK];
__device__ int   g_i1[(size_t)NTOK * HEADS * 2 * TOPK];
__device__ float g_oh[(size_t)NTOK * 1024];

// ---------------- bf16 split helpers ----------------
// split x into hi (rn bf16) + lo (rn bf16 of residual): x ≈ hi + lo, rel ~2^-17
static __device__ __forceinline__ void split_pair_bf16(float x, float y,
                                                       unsigned& hi, unsigned& lo) {
    __nv_bfloat16 xh = __float2bfloat16(x);
    __nv_bfloat16 yh = __float2bfloat16(y);
    __nv_bfloat16 xl = __float2bfloat16(x - __bfloat162float(xh));
    __nv_bfloat16 yl = __float2bfloat16(y - __bfloat162float(yh));
    hi = ((unsigned)__bfloat16_as_ushort(yh) << 16) | (unsigned)__bfloat16_as_ushort(xh);
    lo = ((unsigned)__bfloat16_as_ushort(yl) << 16) | (unsigned)__bfloat16_as_ushort(xl);
}
// m16n8k16 bf16 mma, fp32 accum
static __device__ __forceinline__ void mma16816(float* d, const unsigned* a, const unsigned* b) {
    asm volatile(
        "mma.sync.aligned.m16n8k16.row.col.f32.bf16.bf16.f32 "
        "{%0,%1,%2,%3}, {%4,%5,%6,%7}, {%8,%9}, {%0,%1,%2,%3};"
        : "+f"(d[0]), "+f"(d[1]), "+f"(d[2]), "+f"(d[3])
        : "r"(a[0]), "r"(a[1]), "r"(a[2]), "r"(a[3]), "r"(b[0]), "r"(b[1]));
}

// =================================================================
// Split-bf16 3-mma GEMM (~2^-16 rel, selection-safe AND output-safe):
// C[M,N] = A[M,K] * B[N,K]^T (+ bias). R15-proven schedule: raw fp32
// smem, in-loop convert, double-buffered, 1 sync/iter, no reg cap.
// Block 128x128x16, 8 warps, warp tile 32x64, m16n8k16 HMMA.
// =================================================================
__global__ __launch_bounds__(256)
void mma_bf16x3_tn(const float* __restrict__ A, const float* __restrict__ B,
                   float* __restrict__ C, const float* __restrict__ bias,
                   int M, int N, int K, int lda, int ldb, int ldc)
{
    __shared__ float As[2][128][20];
    __shared__ float Bs[2][128][20];

    const int tid  = threadIdx.x;
    const int lane = tid & 31;
    const int wid  = tid >> 5;
    const int wm   = wid & 3;
    const int wn   = wid >> 2;
    const int m0   = blockIdx.y * 128;
    const int n0   = blockIdx.x * 128;

    const int r0 = tid >> 2;
    const int r1 = r0 + 64;
    const int kc = (tid & 3) << 2;

    const float* Ap0 = A + (size_t)(m0 + r0) * lda + kc;
    const float* Ap1 = A + (size_t)(m0 + r1) * lda + kc;
    const float* Bp0 = B + (size_t)(n0 + r0) * ldb + kc;
    const float* Bp1 = B + (size_t)(n0 + r1) * ldb + kc;

    float4 ra0 = *(const float4*)Ap0;
    float4 ra1 = *(const float4*)Ap1;
    float4 rb0 = *(const float4*)Bp0;
    float4 rb1 = *(const float4*)Bp1;

    float d[2][8][4];
    #pragma unroll
    for (int mt = 0; mt < 2; mt++)
        #pragma unroll
        for (int nt = 0; nt < 8; nt++)
            #pragma unroll
            for (int i = 0; i < 4; i++) d[mt][nt][i] = 0.f;

    const int frow = lane >> 2;     // a-row / b-col group
    const int fcol = lane & 3;      // k-pair id
    const int nsteps = K >> 4;      // K-tile = 16 = one m16n8k16 step

    *(float4*)&As[0][r0][kc] = ra0;
    *(float4*)&As[0][r1][kc] = ra1;
    *(float4*)&Bs[0][r0][kc] = rb0;
    *(float4*)&Bs[0][r1][kc] = rb1;
    __syncthreads();

    for (int s = 0; s < nsteps; s++) {
        const int cur = s & 1;
        const int nxt = cur ^ 1;
        if (s + 1 < nsteps) {       // prefetch next tile (hidden by compute)
            ra0 = *(const float4*)(Ap0 + (s+1)*16);
            ra1 = *(const float4*)(Ap1 + (s+1)*16);
            rb0 = *(const float4*)(Bp0 + (s+1)*16);
            rb1 = *(const float4*)(Bp1 + (s+1)*16);
        }

        // A fragments: rows {frow, frow+8}, k {2fcol,2fcol+1} and +8
        unsigned ah[2][4], al[2][4];
        #pragma unroll
        for (int mt = 0; mt < 2; mt++) {
            const int mb = wm*32 + mt*16;
            float2 x0 = *(const float2*)&As[cur][mb + frow    ][2*fcol    ];
            float2 x1 = *(const float2*)&As[cur][mb + frow + 8][2*fcol    ];
            float2 x2 = *(const float2*)&As[cur][mb + frow    ][2*fcol + 8];
            float2 x3 = *(const float2*)&As[cur][mb + frow + 8][2*fcol + 8];
            split_pair_bf16(x0.x, x0.y, ah[mt][0], al[mt][0]);
            split_pair_bf16(x1.x, x1.y, ah[mt][1], al[mt][1]);
            split_pair_bf16(x2.x, x2.y, ah[mt][2], al[mt][2]);
            split_pair_bf16(x3.x, x3.y, ah[mt][3], al[mt][3]);
        }
        #pragma unroll
        for (int nt = 0; nt < 8; nt++) {
            const int n = wn*64 + nt*8 + frow;
            float2 y0 = *(const float2*)&Bs[cur][n][2*fcol    ];
            float2 y1 = *(const float2*)&Bs[cur][n][2*fcol + 8];
            unsigned bh[2], bl[2];
            split_pair_bf16(y0.x, y0.y, bh[0], bl[0]);
            split_pair_bf16(y1.x, y1.y, bh[1], bl[1]);
            // d += ah*bh + ah*bl + al*bh   (al*bl ~ 2^-32, dropped)
            mma16816(d[0][nt], ah[0], bh);
            mma16816(d[0][nt], ah[0], bl);
            mma16816(d[0][nt], al[0], bh);
            mma16816(d[1][nt], ah[1], bh);
            mma16816(d[1][nt], ah[1], bl);
            mma16816(d[1][nt], al[1], bh);
        }

        if (s + 1 < nsteps) {
            *(float4*)&As[nxt][r0][kc] = ra0;
            *(float4*)&As[nxt][r1][kc] = ra1;
            *(float4*)&Bs[nxt][r0][kc] = rb0;
            *(float4*)&Bs[nxt][r1][kc] = rb1;
        }
        __syncthreads();
    }

    #pragma unroll
    for (int mt = 0; mt < 2; mt++) {
        const int row = m0 + wm*32 + mt*16 + frow;
        #pragma unroll
        for (int nt = 0; nt < 8; nt++) {
            const int col = n0 + wn*64 + nt*8 + fcol*2;
            float2 bv = make_float2(0.f, 0.f);
            if (bias) bv = *(const float2*)(bias + col);
            *(float2*)&C[(size_t)row * ldc + col] =
                make_float2(d[mt][nt][0] + bv.x, d[mt][nt][1] + bv.y);
            *(float2*)&C[(size_t)(row + 8) * ldc + col] =
                make_float2(d[mt][nt][2] + bv.x, d[mt][nt][3] + bv.y);
        }
    }
}

// =================================================================
// Kernel 2: dots (one (h,p), 32-token tile vs 256 keys) + top-32.
// Extraction: 4 interleaved chains/warp, REDUX + ballot per round.
// (unchanged from R15)
// =================================================================
__global__ __launch_bounds__(256)
void dots_topk_kernel(const float* __restrict__ qm, const float* __restrict__ keys)
{
    __shared__ float As[8][36];
    __shared__ float Bs[8][264];
    __shared__ float dsm[32*256];

    const int tid  = threadIdx.x;
    const int hp   = blockIdx.y;
    const int h    = hp >> 1;
    const int p    = hp & 1;
    const int t0g  = blockIdx.x * 32;

    const int ty   = tid >> 5;
    const int lane = tid & 31;

    const int at = tid >> 1;
    const int ak = (tid & 1) << 2;
    const float* Ap = qm + (size_t)(t0g + at) * 2048 + p*1024 + h*DH + ak;

    const int bn0 = tid >> 1;
    const int bn1 = bn0 + 128;
    const int bk  = (tid & 1) << 2;
    const float* Kb  = keys + (size_t)h * (NKEY*2*DH) + (size_t)p * DH;
    const float* Bp0 = Kb + (size_t)bn0 * (2*DH) + bk;
    const float* Bp1 = Kb + (size_t)bn1 * (2*DH) + bk;

    float4 ra = make_float4(0.f,0.f,0.f,0.f);
    if (tid < 64) ra = *(const float4*)Ap;
    float4 rb0 = *(const float4*)Bp0;
    float4 rb1 = *(const float4*)Bp1;

    float acc[4][8];
    #pragma unroll
    for (int r = 0; r < 4; r++)
        #pragma unroll
        for (int c = 0; c < 8; c++) acc[r][c] = 0.f;

    for (int s = 0; s < 16; s++) {
        __syncthreads();
        if (tid < 64) {
            As[ak+0][at] = ra.x; As[ak+1][at] = ra.y;
            As[ak+2][at] = ra.z; As[ak+3][at] = ra.w;
        }
        Bs[bk+0][bn0] = rb0.x; Bs[bk+1][bn0] = rb0.y;
        Bs[bk+2][bn0] = rb0.z; Bs[bk+3][bn0] = rb0.w;
        Bs[bk+0][bn1] = rb1.x; Bs[bk+1][bn1] = rb1.y;
        Bs[bk+2][bn1] = rb1.z; Bs[bk+3][bn1] = rb1.w;
        __syncthreads();
        if (s + 1 < 16) {
            if (tid < 64) ra = *(const float4*)(Ap + (s+1)*8);
            rb0 = *(const float4*)(Bp0 + (s+1)*8);
            rb1 = *(const float4*)(Bp1 + (s+1)*8);
        }
        #pragma unroll
        for (int kk = 0; kk < 8; kk++) {
            float4 a4 = *(const float4*)&As[kk][ty*4];
            float4 b0 = *(const float4*)&Bs[kk][lane*4];
            float4 b1 = *(const float4*)&Bs[kk][128 + lane*4];
            float ar[4] = {a4.x,a4.y,a4.z,a4.w};
            float bc[8] = {b0.x,b0.y,b0.z,b0.w,b1.x,b1.y,b1.z,b1.w};
            #pragma unroll
            for (int r = 0; r < 4; r++)
                #pragma unroll
                for (int c = 0; c < 8; c++)
                    acc[r][c] = fmaf(ar[r], bc[c], acc[r][c]);
        }
    }

    #pragma unroll
    for (int r = 0; r < 4; r++) {
        *(float4*)&dsm[(ty*4+r)*256 + lane*4]       = make_float4(acc[r][0],acc[r][1],acc[r][2],acc[r][3]);
        *(float4*)&dsm[(ty*4+r)*256 + 128 + lane*4] = make_float4(acc[r][4],acc[r][5],acc[r][6],acc[r][7]);
    }
    __syncthreads();

    float v[4][8];
    #pragma unroll
    for (int c = 0; c < 4; c++)
        #pragma unroll
        for (int j = 0; j < 8; j++)
            v[c][j] = dsm[(ty*4+c)*256 + j*32 + lane];

    unsigned taken[4] = {0u,0u,0u,0u};
    float outv[4] = {0.f,0.f,0.f,0.f};
    int   outn[4] = {0,0,0,0};

    #pragma unroll 1
    for (int kk = 0; kk < 32; kk++) {
        unsigned u[4]; int ln[4];
        #pragma unroll
        for (int c = 0; c < 4; c++) {
            float lv = neg_inf(); int l = 0x7fffffff;
            #pragma unroll
            for (int j = 0; j < 8; j++) {
                float cand = ((taken[c] >> j) & 1u) ? neg_inf() : v[c][j];
                if (cand > lv) { lv = cand; l = j*32 + lane; }
            }
            u[c] = ford(lv); ln[c] = l;
        }
        unsigned umax[4];
        #pragma unroll
        for (int c = 0; c < 4; c++) umax[c] = __reduce_max_sync(0xffffffffu, u[c]);
        unsigned ball[4];
        #pragma unroll
        for (int c = 0; c < 4; c++) ball[c] = __ballot_sync(0xffffffffu, u[c] == umax[c]);
        #pragma unroll
        for (int c = 0; c < 4; c++) {
            const int wl = __ffs(ball[c]) - 1;
            const int wn = __shfl_sync(0xffffffffu, ln[c], wl);
            if (kk == lane) { outv[c] = forddec(umax[c]); outn[c] = wn; }
            if (wl == lane) taken[c] |= 1u << (ln[c] >> 5);
        }
    }

    #pragma unroll
    for (int c = 0; c < 4; c++) {
        const size_t base = ((((size_t)(t0g + ty*4 + c)) * HEADS + h) * 2 + p) * TOPK;
        g_s1[base + lane] = outv[c];
        g_i1[base + lane] = outn[c];
    }
}

// =================================================================
// Kernel 3: combine, 2 slots/warp, software-pipelined gather.
// (unchanged from R15)
// =================================================================
__global__ __launch_bounds__(256)
void combine_kernel(const float* __restrict__ values)
{
    const int warp  = threadIdx.x >> 5;
    const int lane  = threadIdx.x & 31;
    const int slotA = blockIdx.x * 16 + warp * 2;
    const int t  = slotA & 2047;
    const int h  = (slotA >> 11) & 7;
    const int b  = slotA >> 14;
    const int u  = t >> 1;

    const size_t b0A = ((((size_t)(b*2048 + u))        * HEADS + h) * 2 + 0) * TOPK;
    const size_t b1A = ((((size_t)(b*2048 + u + 1024)) * HEADS + h) * 2 + 0) * TOPK;
    const size_t b0B = b0A + TOPK;
    const size_t b1B = b1A + TOPK;

    const float s0A = g_s1[b0A + lane]; const int i0A = g_i1[b0A + lane];
    const float s1A = g_s1[b1A + lane]; const int i1A = g_i1[b1A + lane];
    const float s0B = g_s1[b0B + lane]; const int i0B = g_i1[b0B + lane];
    const float s1B = g_s1[b1B + lane]; const int i1B = g_i1[b1B + lane];

    int ptrA = 0, ptrB = 0;
    float rvA = 0.f, rvB = 0.f; int rfA = 0, rfB = 0;
    #pragma unroll 1
    for (int it = 0; it < 32; it++) {
        const int ppA = ptrA < 32 ? ptrA : 31;
        const int ppB = ptrB < 32 ? ptrB : 31;
        float cvA = __shfl_sync(0xffffffffu, s0A, ppA) + s1A;
        float cvB = __shfl_sync(0xffffffffu, s0B, ppB) + s1B;
        int flA = ptrA * 32 + lane;
        int flB = ptrB * 32 + lane;
        if (ptrA >= 32) { cvA = neg_inf(); flA = 0x7fffffff; }
        if (ptrB >= 32) { cvB = neg_inf(); flB = 0x7fffffff; }
        const unsigned uA = ford(cvA), uB = ford(cvB);
        const unsigned umA = __reduce_max_sync(0xffffffffu, uA);
        const unsigned umB = __reduce_max_sync(0xffffffffu, uB);
        const unsigned baA = __ballot_sync(0xffffffffu, uA == umA);
        const unsigned baB = __ballot_sync(0xffffffffu, uB == umB);
        const int wlA = __ffs(baA) - 1;
        const int wlB = __ffs(baB) - 1;
        const int wfA = __shfl_sync(0xffffffffu, flA, wlA);
        const int wfB = __shfl_sync(0xffffffffu, flB, wlB);
        if (it == lane) { rvA = forddec(umA); rfA = wfA;
                          rvB = forddec(umB); rfB = wfB; }
        if (wlA == lane && flA != 0x7fffffff) ptrA++;
        if (wlB == lane && flB != 0x7fffffff) ptrB++;
    }

    const float mxA = __shfl_sync(0xffffffffu, rvA, 0);
    const float mxB = __shfl_sync(0xffffffffu, rvB, 0);
    float eA = __expf(rvA - mxA);
    float eB = __expf(rvB - mxB);
    float sA = eA, sB = eB;
    #pragma unroll
    for (int o = 16; o > 0; o >>= 1) {
        sA += __shfl_xor_sync(0xffffffffu, sA, o);
        sB += __shfl_xor_sync(0xffffffffu, sB, o);
    }
    const float wA = eA / sA;
    const float wB = eB / sB;

    const int viA = __shfl_sync(0xffffffffu, i0A, rfA >> 5) * NKEY
                  + __shfl_sync(0xffffffffu, i1A, rfA & 31);
    const int viB = __shfl_sync(0xffffffffu, i0B, rfB >> 5) * NKEY
                  + __shfl_sync(0xffffffffu, i1B, rfB & 31);

    const float* vb = values + (size_t)h * ((size_t)NKEY*NKEY) * DH;
    float4 accA = make_float4(0.f,0.f,0.f,0.f);
    float4 accB = make_float4(0.f,0.f,0.f,0.f);

    #pragma unroll 1
    for (int k0 = 0; k0 < 32; k0 += 8) {
        int   iA[8], iB[8];
        float fA[8], fB[8];
        #pragma unroll
        for (int j = 0; j < 8; j++) {
            iA[j] = __shfl_sync(0xffffffffu, viA, k0 + j);
            fA[j] = __shfl_sync(0xffffffffu, wA,  k0 + j);
            iB[j] = __shfl_sync(0xffffffffu, viB, k0 + j);
            fB[j] = __shfl_sync(0xffffffffu, wB,  k0 + j);
        }
        float4 rA[8], rB[8];
        #pragma unroll
        for (int j = 0; j < 8; j++) {
            rA[j] = *(const float4*)(vb + (size_t)iA[j] * DH + lane*4);
            rB[j] = *(const float4*)(vb + (size_t)iB[j] * DH + lane*4);
        }
        #pragma unroll
        for (int j = 0; j < 8; j++) {
            accA.x = fmaf(fA[j], rA[j].x, accA.x);
            accA.y = fmaf(fA[j], rA[j].y, accA.y);
            accA.z = fmaf(fA[j], rA[j].z, accA.z);
            accA.w = fmaf(fA[j], rA[j].w, accA.w);
            accB.x = fmaf(fB[j], rB[j].x, accB.x);
            accB.y = fmaf(fB[j], rB[j].y, accB.y);
            accB.z = fmaf(fB[j], rB[j].z, accB.z);
            accB.w = fmaf(fB[j], rB[j].w, accB.w);
        }
    }

    *(float4*)&g_oh[(size_t)(b*2048 + t)     * 1024 + h*DH + lane*4] = accA;
    *(float4*)&g_oh[(size_t)(b*2048 + t + 1) * 1024 + h*DH + lane*4] = accB;
}

// =================================================================
extern "C" void kernel_launch(void* const* d_in, const int* in_sizes, int n_in,
                              void* d_out, int out_size)
{
    const float* x      = (const float*)d_in[0];
    const float* Wq     = (const float*)d_in[1];
    const float* keys   = (const float*)d_in[2];
    const float* values = (const float*)d_in[3];
    const float* Wo     = (const float*)d_in[4];
    const float* bo     = (const float*)d_in[5];
    float* out = (float*)d_out;

    float* q;  cudaGetSymbolAddress((void**)&q,  g_q);
    float* oh; cudaGetSymbolAddress((void**)&oh, g_oh);

    // 1) q = x @ Wq^T (bf16x3 split: ~2^-16 rel, selection-safe)
    mma_bf16x3_tn<<<dim3(2048/128, 4096/128), 256>>>(x, Wq, q, nullptr,
                                                     4096, 2048, 1024, 1024, 1024, 2048);
    // 2) dots + stage-1 top-32
    dots_topk_kernel<<<dim3(4096/32, 16), 256>>>(q, keys);
    // 3) combine + softmax + gather
    combine_kernel<<<2048, 256>>>(values);
    // 4) out = oh @ Wo^T + bo (bf16x3: more accurate than tf32 single-pass)
    mma_bf16x3_tn<<<dim3(1024/128, 4096/128), 256>>>(oh, Wo, out, bo,
                                                     4096, 1024, 1024, 1024, 1024, 1024);
}